// round 1
// baseline (speedup 1.0000x reference)
#include <cuda_runtime.h>
#include <cuda_bf16.h>
#include <cstdint>

// Problem constants (from reference): N=50000, E=800000, dims 64/128/2.
#define MAXN 50176
#define MAXE 800000

// -------- device scratch (no allocations allowed) --------
__device__ float g_xw[MAXN * 128];     // per-layer x@W result
__device__ float g_H[MAXN * 384];      // concat(h1,h2,h3), row stride 384
__device__ float g_R[MAXN * 384];      // relu(h@lW1^T + lb1)
__device__ int   g_deg[MAXN];
__device__ float g_dinv[MAXN];
__device__ int   g_rp[MAXN + 1];       // CSR row pointers (by dst)
__device__ int   g_cur[MAXN];          // fill cursors
__device__ int   g_col[MAXE];          // CSR: src node per slot
__device__ int   g_bsums[64];

// ======================= graph preprocessing =======================

__global__ void k_zero_deg(int n) {
    int i = blockIdx.x * blockDim.x + threadIdx.x;
    if (i < n) g_deg[i] = 0;
}

__global__ void k_deg(const int* __restrict__ dst, int e) {
    int i = blockIdx.x * blockDim.x + threadIdx.x;
    if (i < e) atomicAdd(&g_deg[dst[i]], 1);
}

__global__ void k_dinv(int n) {
    int i = blockIdx.x * blockDim.x + threadIdx.x;
    if (i < n) g_dinv[i] = rsqrtf((float)(g_deg[i] + 1));  // +1 self-loop
}

__global__ void k_scan1(int n) {
    __shared__ int sh[1024];
    int i = blockIdx.x * 1024 + threadIdx.x;
    int v = (i < n) ? g_deg[i] : 0;
    sh[threadIdx.x] = v;
    __syncthreads();
    for (int o = 1; o < 1024; o <<= 1) {
        int t = (threadIdx.x >= o) ? sh[threadIdx.x - o] : 0;
        __syncthreads();
        sh[threadIdx.x] += t;
        __syncthreads();
    }
    int incl = sh[threadIdx.x];
    if (i < n) g_rp[i] = incl - v;                // exclusive within block
    if (threadIdx.x == 1023) g_bsums[blockIdx.x] = incl;
}

__global__ void k_scan2(int nb) {
    __shared__ int sh[64];
    int v = (threadIdx.x < nb) ? g_bsums[threadIdx.x] : 0;
    sh[threadIdx.x] = v;
    __syncthreads();
    for (int o = 1; o < 64; o <<= 1) {
        int t = (threadIdx.x >= o) ? sh[threadIdx.x - o] : 0;
        __syncthreads();
        sh[threadIdx.x] += t;
        __syncthreads();
    }
    if (threadIdx.x < nb) g_bsums[threadIdx.x] = sh[threadIdx.x] - v;  // exclusive
}

__global__ void k_scan3(int n, int e) {
    int i = blockIdx.x * 1024 + threadIdx.x;
    if (i < n) {
        int v = g_rp[i] + g_bsums[blockIdx.x];
        g_rp[i] = v;
        g_cur[i] = v;
    }
    if (i == 0) g_rp[n] = e;
}

__global__ void k_fill(const int* __restrict__ src, const int* __restrict__ dst, int e) {
    int i = blockIdx.x * blockDim.x + threadIdx.x;
    if (i < e) {
        int s = src[i], d = dst[i];
        int p = atomicAdd(&g_cur[d], 1);
        g_col[p] = s;
    }
}

// ======================= fp32 SGEMM (BM=128,BN=128,BK=8, 8x8 microtile) =====

template <bool TRANSB, int EPI>
__global__ __launch_bounds__(256)
void sgemm128(const float* __restrict__ A, int lda,
              const float* __restrict__ B, int ldb,
              float* __restrict__ C, int ldc,
              const float* __restrict__ bias,
              int M, int K)
{
    const int BK = 8, TM = 8, TN = 8;
    __shared__ float As[BK][128];
    __shared__ float Bs[BK][128];
    int bm = blockIdx.x * 128;
    int bn = blockIdx.y * 128;
    int t  = threadIdx.x;
    int tx = t & 15, ty = t >> 4;

    float acc[TM][TN] = {};

    int arow = t >> 1;            // 0..127
    int acol = (t & 1) * 4;       // 0 or 4
    int brow = t >> 5;            // 0..7
    int bcol = (t & 31) * 4;      // 0..124
    int tcol = t & 127;           // 0..127  (trans path: n index)
    int tk   = (t >> 7) * 4;      // 0 or 4

    for (int k0 = 0; k0 < K; k0 += BK) {
        float4 av = make_float4(0.f, 0.f, 0.f, 0.f);
        if (bm + arow < M)
            av = *(const float4*)(A + (size_t)(bm + arow) * lda + k0 + acol);
        As[acol + 0][arow] = av.x;
        As[acol + 1][arow] = av.y;
        As[acol + 2][arow] = av.z;
        As[acol + 3][arow] = av.w;

        if (!TRANSB) {
            float4 bv = *(const float4*)(B + (size_t)(k0 + brow) * ldb + bn + bcol);
            *(float4*)&Bs[brow][bcol] = bv;
        } else {
            // B element (k, n) = Bsrc[n * ldb + k]  (torch Linear weight [out,in])
            float4 bv = *(const float4*)(B + (size_t)(bn + tcol) * ldb + k0 + tk);
            Bs[tk + 0][tcol] = bv.x;
            Bs[tk + 1][tcol] = bv.y;
            Bs[tk + 2][tcol] = bv.z;
            Bs[tk + 3][tcol] = bv.w;
        }
        __syncthreads();

#pragma unroll
        for (int kk = 0; kk < BK; ++kk) {
            float ra[TM], rb[TN];
#pragma unroll
            for (int i = 0; i < TM; ++i) ra[i] = As[kk][ty * TM + i];
#pragma unroll
            for (int j = 0; j < TN; ++j) rb[j] = Bs[kk][tx * TN + j];
#pragma unroll
            for (int i = 0; i < TM; ++i)
#pragma unroll
                for (int j = 0; j < TN; ++j)
                    acc[i][j] += ra[i] * rb[j];
        }
        __syncthreads();
    }

#pragma unroll
    for (int i = 0; i < TM; ++i) {
        int row = bm + ty * TM + i;
        if (row >= M) continue;
#pragma unroll
        for (int j = 0; j < TN; j += 4) {
            int c0 = bn + tx * TN + j;
            float4 v = make_float4(acc[i][j], acc[i][j + 1], acc[i][j + 2], acc[i][j + 3]);
            if (EPI == 1) {
                v.x = fmaxf(v.x + bias[c0 + 0], 0.f);
                v.y = fmaxf(v.y + bias[c0 + 1], 0.f);
                v.z = fmaxf(v.z + bias[c0 + 2], 0.f);
                v.w = fmaxf(v.w + bias[c0 + 3], 0.f);
            }
            *(float4*)(C + (size_t)row * ldc + c0) = v;
        }
    }
}

// ======================= edge aggregation (warp per dst node) ===============
// H[node, off + f] = dinv[node]^2 * xw[node,f] + sum_{e: dst=node} dinv[src]*dinv[node]*xw[src,f] + b[f]

__global__ void k_agg(const float* __restrict__ bias, float* __restrict__ H,
                      int off, int n)
{
    int warp = (blockIdx.x * blockDim.x + threadIdx.x) >> 5;
    int lane = threadIdx.x & 31;
    if (warp >= n) return;
    const float4* xw4 = (const float4*)g_xw;
    float di = g_dinv[warp];
    float4 a = xw4[(size_t)warp * 32 + lane];
    float w0 = di * di;
    float4 acc = make_float4(a.x * w0, a.y * w0, a.z * w0, a.w * w0);
    int s0 = g_rp[warp], s1 = g_rp[warp + 1];
    for (int j = s0; j < s1; ++j) {
        int s = g_col[j];
        float w = di * g_dinv[s];
        float4 v = xw4[(size_t)s * 32 + lane];
        acc.x += w * v.x;
        acc.y += w * v.y;
        acc.z += w * v.z;
        acc.w += w * v.w;
    }
    float4 b4 = ((const float4*)bias)[lane];
    acc.x += b4.x; acc.y += b4.y; acc.z += b4.z; acc.w += b4.w;
    *(float4*)(H + (size_t)warp * 384 + off + lane * 4) = acc;
}

// ======================= final linear (384->2) + softmax ====================

__global__ void k_final(const float* __restrict__ lW2, const float* __restrict__ lb2,
                        float* __restrict__ out, int n)
{
    __shared__ float w2s[770];
    for (int i = threadIdx.x; i < 768; i += blockDim.x) w2s[i] = lW2[i];
    if (threadIdx.x < 2) w2s[768 + threadIdx.x] = lb2[threadIdx.x];
    __syncthreads();
    int warp = (blockIdx.x * blockDim.x + threadIdx.x) >> 5;
    int lane = threadIdx.x & 31;
    if (warp >= n) return;
    const float* r = g_R + (size_t)warp * 384;
    float a0 = 0.f, a1 = 0.f;
#pragma unroll
    for (int i = lane; i < 384; i += 32) {
        float v = r[i];
        a0 += v * w2s[i];
        a1 += v * w2s[384 + i];
    }
#pragma unroll
    for (int o = 16; o; o >>= 1) {
        a0 += __shfl_xor_sync(0xFFFFFFFFu, a0, o);
        a1 += __shfl_xor_sync(0xFFFFFFFFu, a1, o);
    }
    if (lane == 0) {
        a0 += w2s[768];
        a1 += w2s[769];
        out[(size_t)warp * 2 + 0] = a0;
        out[(size_t)warp * 2 + 1] = a1;
        float m = fmaxf(a0, a1);
        float e0 = expf(a0 - m), e1 = expf(a1 - m);
        float inv = 1.f / (e0 + e1);
        out[(size_t)2 * n + warp * 2 + 0] = e0 * inv;
        out[(size_t)2 * n + warp * 2 + 1] = e1 * inv;
    }
}

// ======================= launch =======================

extern "C" void kernel_launch(void* const* d_in, const int* in_sizes, int n_in,
                              void* d_out, int out_size)
{
    const float* x   = (const float*)d_in[0];
    const int*   ei  = (const int*)  d_in[1];
    const float* W1  = (const float*)d_in[2];
    const float* b1  = (const float*)d_in[3];
    const float* W2  = (const float*)d_in[4];
    const float* b2  = (const float*)d_in[5];
    const float* W3  = (const float*)d_in[6];
    const float* b3  = (const float*)d_in[7];
    const float* lW1 = (const float*)d_in[8];
    const float* lb1 = (const float*)d_in[9];
    const float* lW2 = (const float*)d_in[10];
    const float* lb2 = (const float*)d_in[11];
    float* out = (float*)d_out;

    int n = in_sizes[0] / 64;   // 50000
    int e = in_sizes[1] / 2;    // 800000
    const int* src = ei;
    const int* dst = ei + e;

    void *p_xw, *p_H, *p_R;
    cudaGetSymbolAddress(&p_xw, g_xw);
    cudaGetSymbolAddress(&p_H,  g_H);
    cudaGetSymbolAddress(&p_R,  g_R);
    float* xw = (float*)p_xw;
    float* H  = (float*)p_H;
    float* R  = (float*)p_R;

    int nb = (n + 1023) / 1024;

    // --- CSR build ---
    k_zero_deg<<<(n + 255) / 256, 256>>>(n);
    k_deg<<<(e + 255) / 256, 256>>>(dst, e);
    k_dinv<<<(n + 255) / 256, 256>>>(n);
    k_scan1<<<nb, 1024>>>(n);
    k_scan2<<<1, 64>>>(nb);
    k_scan3<<<nb, 1024>>>(n, e);
    k_fill<<<(e + 255) / 256, 256>>>(src, dst, e);

    int gm = (n + 127) / 128;          // 391
    int aggBlocks = (n + 7) / 8;       // 8 warps/block

    // --- conv1 ---
    sgemm128<false, 0><<<dim3(gm, 1), 256>>>(x, 64, W1, 128, xw, 128, nullptr, n, 64);
    k_agg<<<aggBlocks, 256>>>(b1, H, 0, n);
    // --- conv2 ---
    sgemm128<false, 0><<<dim3(gm, 1), 256>>>(H + 0, 384, W2, 128, xw, 128, nullptr, n, 128);
    k_agg<<<aggBlocks, 256>>>(b2, H, 128, n);
    // --- conv3 ---
    sgemm128<false, 0><<<dim3(gm, 1), 256>>>(H + 128, 384, W3, 128, xw, 128, nullptr, n, 128);
    k_agg<<<aggBlocks, 256>>>(b3, H, 256, n);

    // --- MLP: relu(H @ lW1^T + lb1) ---
    sgemm128<true, 1><<<dim3(gm, 3), 256>>>(H, 384, lW1, 384, R, 384, lb1, n, 384);

    // --- lW2 + softmax ---
    k_final<<<aggBlocks, 256>>>(lW2, lb2, out, n);
}